// round 5
// baseline (speedup 1.0000x reference)
#include <cuda_runtime.h>
#include <cuda_bf16.h>
#include <cstdint>

typedef unsigned long long ull;

#define NB 128
#define NN 1024
#define NT 16          // 64-wide tiles per dim

// Device scratch (no allocs allowed)
__device__ float g_Ut[NN * NN];      // Ut[j][i] = (i<=j) ? W[i][j] : 0   (4 MB)
__device__ float g_VT[NN * NB];      // VT[j][x] = V[x][j]                (0.5 MB)
__device__ float g_rc[NN];           // rc[i] = rowsum_i(U) + colsum_i(U)

#define FMA2(d, a, b, c) \
    asm("fma.rn.f32x2 %0, %1, %2, %3;" : "=l"(d) : "l"(a), "l"(b), "l"(c))

__device__ __forceinline__ ull pack2(float f) {
    ull r;
    unsigned int u = __float_as_uint(f);
    asm("mov.b64 %0, {%1, %1};" : "=l"(r) : "r"(u));
    return r;
}
__device__ __forceinline__ void unpack2(ull s, float& lo, float& hi) {
    unsigned int a, b;
    asm("mov.b64 {%0, %1}, %2;" : "=r"(a), "=r"(b) : "l"(s));
    lo = __uint_as_float(a);
    hi = __uint_as_float(b);
}

// ---- P2: transpose V -> VT, and zero rc.  grid (32,4), block (32,8) ----
__global__ void prep_v_kernel(const float* __restrict__ V) {
    __shared__ float ts[32][33];
    const int tx = threadIdx.x, ty = threadIdx.y;
    const int J0 = blockIdx.x * 32, X0 = blockIdx.y * 32;

    if (blockIdx.y == 0 && ty == 0) g_rc[blockIdx.x * 32 + tx] = 0.0f;

    #pragma unroll
    for (int q = 0; q < 4; ++q)
        ts[ty + 8 * q][tx] = V[(size_t)(X0 + ty + 8 * q) * NN + J0 + tx];  // coalesced
    __syncthreads();
    #pragma unroll
    for (int q = 0; q < 4; ++q) {
        int j = ty + 8 * q;
        g_VT[(size_t)(J0 + j) * NB + X0 + tx] = ts[tx][j];                 // coalesced
    }
}

// ---- P1: masked transpose of W -> Ut, + rc sums. grid (32,32), block (32,8) ----
__global__ void prep_w_kernel(const float* __restrict__ W) {
    __shared__ float ts[32][33];
    const int tx = threadIdx.x, ty = threadIdx.y;
    const int I0 = blockIdx.y * 32, J0 = blockIdx.x * 32;

    #pragma unroll
    for (int q = 0; q < 4; ++q) {
        int gi = I0 + ty + 8 * q, gj = J0 + tx;
        float w = W[(size_t)gi * NN + gj];            // coalesced
        ts[ty + 8 * q][tx] = (gi <= gj) ? w : 0.0f;
    }
    __syncthreads();
    #pragma unroll
    for (int q = 0; q < 4; ++q) {
        int j = ty + 8 * q;
        g_Ut[(size_t)(J0 + j) * NN + I0 + tx] = ts[tx][j];   // coalesced
    }
    if (ty == 0) {            // row sums of U over this j-tile -> rc[I0+tx]
        float s = 0.0f;
        #pragma unroll 8
        for (int j = 0; j < 32; ++j) s += ts[tx][j];
        atomicAdd(&g_rc[I0 + tx], s);
    } else if (ty == 1) {     // col sums of U over this i-tile -> rc[J0+tx]
        float s = 0.0f;
        #pragma unroll 8
        for (int i = 0; i < 32; ++i) s += ts[i][tx];
        atomicAdd(&g_rc[J0 + tx], s);
    }
}

// ---- Q: quad + linear terms. 544 blocks = 136 upper tiles x 4 k-quarters. ----
// Block: 128 threads, per-thread 8i x 8x, k depth 16. No smem, no syncs.
// energy_b = sum_i rc_i*(0.5 - v_bi) + 2 * v_b^T U v_b
__global__ void __launch_bounds__(128, 4)
quad_kernel(float* __restrict__ out) {
    int bid = blockIdx.x;
    int kq  = bid & 3;
    int h   = bid >> 2;             // 0..135
    int ti  = 0;
    while (h >= NT - ti) { h -= NT - ti; ++ti; }
    int tj  = ti + h;

    const int tid = threadIdx.x;
    const int I0 = ti * 64;
    const int J0 = tj * 64 + kq * 16;

    const int ig = tid & 7;         // i-group: 8 i's as 4 pairs
    const int xg = tid >> 3;        // x-group: 0..15, 8 x's each
    const int i0 = ig * 8;
    const int x0 = xg * 8;

    const float* Wp = g_Ut + (size_t)J0 * NN + I0 + i0;
    const float* Vp = g_VT + (size_t)J0 * NB + x0;

    ull acc[4][8];
    #pragma unroll
    for (int p = 0; p < 4; ++p)
        #pragma unroll
        for (int xx = 0; xx < 8; ++xx) acc[p][xx] = 0ull;

    #pragma unroll 8
    for (int k = 0; k < 16; ++k) {
        ulonglong2 wA = *reinterpret_cast<const ulonglong2*>(Wp + (size_t)k * NN);
        ulonglong2 wB = *reinterpret_cast<const ulonglong2*>(Wp + (size_t)k * NN + 4);
        float4 vA = *reinterpret_cast<const float4*>(Vp + (size_t)k * NB);
        float4 vB = *reinterpret_cast<const float4*>(Vp + (size_t)k * NB + 4);
        const ull w_[4] = {wA.x, wA.y, wB.x, wB.y};      // (w_i, w_i+1) pairs
        const ull v_[8] = {pack2(vA.x), pack2(vA.y), pack2(vA.z), pack2(vA.w),
                           pack2(vB.x), pack2(vB.y), pack2(vB.z), pack2(vB.w)};
        #pragma unroll
        for (int p = 0; p < 4; ++p)
            #pragma unroll
            for (int xx = 0; xx < 8; ++xx)
                FMA2(acc[p][xx], w_[p], v_[xx], acc[p][xx]);
    }

    // epilogue: s[x] = sum_i VT[I0+i][x] * C[i][x]
    const float* Xp = g_VT + (size_t)(I0 + i0) * NB + x0;
    float s[8] = {0, 0, 0, 0, 0, 0, 0, 0};
    #pragma unroll
    for (int p = 0; p < 4; ++p) {
        float4 la = *reinterpret_cast<const float4*>(Xp + (size_t)(2 * p) * NB);
        float4 lb = *reinterpret_cast<const float4*>(Xp + (size_t)(2 * p) * NB + 4);
        float4 ha = *reinterpret_cast<const float4*>(Xp + (size_t)(2 * p + 1) * NB);
        float4 hb = *reinterpret_cast<const float4*>(Xp + (size_t)(2 * p + 1) * NB + 4);
        const float xl[8] = {la.x, la.y, la.z, la.w, lb.x, lb.y, lb.z, lb.w};
        const float xh[8] = {ha.x, ha.y, ha.z, ha.w, hb.x, hb.y, hb.z, hb.w};
        #pragma unroll
        for (int xx = 0; xx < 8; ++xx) {
            float clo, chi;
            unpack2(acc[p][xx], clo, chi);
            s[xx] += xl[xx] * clo + xh[xx] * chi;
        }
    }
    #pragma unroll
    for (int off = 4; off >= 1; off >>= 1)
        #pragma unroll
        for (int xx = 0; xx < 8; ++xx)
            s[xx] += __shfl_xor_sync(0xffffffffu, s[xx], off, 8);

    if (ig == 0) {
        #pragma unroll
        for (int xx = 0; xx < 8; ++xx)
            atomicAdd(&out[x0 + xx], 2.0f * s[xx]);     // fire-and-forget -> REDG
    }

    // linear + constant, spread over blocks 0..63 (16 i's each)
    if (bid < 64) {
        const int b = tid;              // 0..127
        const int ib = bid * 16;
        float e = 0.0f;
        #pragma unroll
        for (int q = 0; q < 16; ++q) {
            int i = ib + q;
            e += g_rc[i] * (0.5f - g_VT[(size_t)i * NB + b]);   // coalesced over b
        }
        atomicAdd(&out[b], e);
    }
}

extern "C" void kernel_launch(void* const* d_in, const int* in_sizes, int n_in,
                              void* d_out, int out_size) {
    const float* V = (const float*)d_in[0];   // vector       [128,1024]
    const float* W = (const float*)d_in[1];   // interactions [1024,1024]
    if (n_in >= 2 && in_sizes[0] > in_sizes[1]) {
        V = (const float*)d_in[1];
        W = (const float*)d_in[0];
    }
    float* out = (float*)d_out;

    cudaMemsetAsync(out, 0, (size_t)out_size * sizeof(float));
    prep_v_kernel<<<dim3(32, 4),  dim3(32, 8)>>>(V);   // VT + rc zero
    prep_w_kernel<<<dim3(32, 32), dim3(32, 8)>>>(W);   // Ut + rc sums
    const int nblocks = (NT * (NT + 1) / 2) * 4;       // 136 x 4 = 544
    quad_kernel<<<nblocks, 128>>>(out);
}

// round 6
// speedup vs baseline: 2.2953x; 2.2953x over previous
#include <cuda_runtime.h>
#include <cuda_bf16.h>
#include <cstdint>

typedef unsigned long long ull;

#define NB 128
#define NN 1024
#define NT 16          // 64-wide tiles per dim
#define WS 68          // Wt row stride (floats): 64 + skew gap + pad
#define VS2 260        // V2 row stride (floats): 256 dup + pad

#define FMA2(d, a, b, c) \
    asm("fma.rn.f32x2 %0, %1, %2, %3;" : "=l"(d) : "l"(a), "l"(b), "l"(c))
#define ADD2(d, a, b) \
    asm("add.rn.f32x2 %0, %1, %2;" : "=l"(d) : "l"(a), "l"(b))

__device__ __forceinline__ void unpack2(ull s, float& lo, float& hi) {
    unsigned int a, b;
    asm("mov.b64 {%0, %1}, %2;" : "=r"(a), "=r"(b) : "l"(s));
    lo = __uint_as_float(a);
    hi = __uint_as_float(b);
}

// Per (64x64 upper-tri tile, 32-wide j-half):
//   C[i,x]  = sum_j U_ij * v_xj
//   rt_i    = sum_j U_ij
//   e_x    += 2*sum_i v_xi*C[i,x] - sum_i C[i,x] - sum_i rt_i*v_xi + sum_i rt_i
// Summed over all tiles this equals energy_b (b = x).
__global__ void __launch_bounds__(256, 3)
potts_kernel(const float* __restrict__ V, const float* __restrict__ W,
             float* __restrict__ out)
{
    // decode (ti, tj, kh) from linear upper-tri block id
    int bid = blockIdx.x;
    int kh  = bid & 1;
    int h   = bid >> 1;            // 0..135
    int ti  = 0;
    while (h >= NT - ti) { h -= NT - ti; ++ti; }
    int tj  = ti + h;

    __shared__ float Wt[32 * WS];      // Wt[j][i'] (i' skewed), 8.7 KB
    __shared__ float V2[32 * VS2];     // V2[j][2x] = (v,v),     33.3 KB

    const int tid = threadIdx.x;
    const int I0 = ti * 64;
    const int J0 = tj * 64 + kh * 32;

    // ---- Fill Wt: masked-triu, transposed, i-skewed ----
    // thread: i = tid>>3 (+32 on 2nd iter), j4 = tid&7 -> coalesced LDG.128
    {
        const int j4 = tid & 7;
        #pragma unroll
        for (int it = 0; it < 2; ++it) {
            int i  = (tid >> 3) + 32 * it;
            int gi = I0 + i;
            int j  = 4 * j4;
            float4 w4 = *reinterpret_cast<const float4*>(W + (size_t)gi * NN + J0 + j);
            int gj = J0 + j;
            int ip = i + 4 * (i >> 5);             // skew: distinct bank quads
            Wt[(j + 0) * WS + ip] = (gi <= gj + 0) ? w4.x : 0.0f;
            Wt[(j + 1) * WS + ip] = (gi <= gj + 1) ? w4.y : 0.0f;
            Wt[(j + 2) * WS + ip] = (gi <= gj + 2) ? w4.z : 0.0f;
            Wt[(j + 3) * WS + ip] = (gi <= gj + 3) ? w4.w : 0.0f;
        }
    }
    // ---- Fill V2[j][2x] = (v,v): thread x = tid>>1, jh = tid&1 ----
    {
        const int x  = tid >> 1;
        const int jh = tid & 1;
        const float* Vx = V + (size_t)x * NN + J0 + 16 * jh;
        #pragma unroll
        for (int q = 0; q < 4; ++q) {
            float4 v4 = *reinterpret_cast<const float4*>(Vx + 4 * q);
            int j = 16 * jh + 4 * q;
            *reinterpret_cast<float2*>(&V2[(j + 0) * VS2 + 2 * x]) = make_float2(v4.x, v4.x);
            *reinterpret_cast<float2*>(&V2[(j + 1) * VS2 + 2 * x]) = make_float2(v4.y, v4.y);
            *reinterpret_cast<float2*>(&V2[(j + 2) * VS2 + 2 * x]) = make_float2(v4.z, v4.z);
            *reinterpret_cast<float2*>(&V2[(j + 3) * VS2 + 2 * x]) = make_float2(v4.w, v4.w);
        }
    }
    __syncthreads();

    // ---- Inner loop: 8 i (4 pairs) x 4 x per thread over 32 j ----
    const int ig = tid & 7;                       // i-group
    const int xg = tid >> 3;                      // x-group 0..31
    const int i0 = ig * 8;                        // true i base
    const int i0p = i0 + 4 * (ig >> 2);           // skewed smem i base
    const int x0 = xg * 4;

    const float* WtP = Wt + i0p;
    const float* VtP = V2 + 8 * xg;

    ull acc[4][4];
    ull rt[4];
    #pragma unroll
    for (int p = 0; p < 4; ++p) {
        rt[p] = 0ull;
        #pragma unroll
        for (int xx = 0; xx < 4; ++xx) acc[p][xx] = 0ull;
    }

    #pragma unroll 8
    for (int k = 0; k < 32; ++k) {
        ulonglong2 wA = *reinterpret_cast<const ulonglong2*>(WtP + (size_t)k * WS);
        ulonglong2 wB = *reinterpret_cast<const ulonglong2*>(WtP + (size_t)k * WS + 4);
        ulonglong2 vA = *reinterpret_cast<const ulonglong2*>(VtP + (size_t)k * VS2);
        ulonglong2 vB = *reinterpret_cast<const ulonglong2*>(VtP + (size_t)k * VS2 + 4);
        const ull w_[4] = {wA.x, wA.y, wB.x, wB.y};   // (w_i, w_i+1) pairs
        const ull v_[4] = {vA.x, vA.y, vB.x, vB.y};   // (v_x, v_x) dups
        #pragma unroll
        for (int p = 0; p < 4; ++p) {
            ADD2(rt[p], rt[p], w_[p]);
            #pragma unroll
            for (int xx = 0; xx < 4; ++xx)
                FMA2(acc[p][xx], w_[p], v_[xx], acc[p][xx]);
        }
    }

    // ---- Epilogue ----
    // S0 partial (sum of rt over this thread's 8 i's)
    float s0 = 0.0f;
    float rlo[4], rhi[4];
    #pragma unroll
    for (int p = 0; p < 4; ++p) {
        unpack2(rt[p], rlo[p], rhi[p]);
        s0 += rlo[p] + rhi[p];
    }

    float e[4];
    #pragma unroll
    for (int xx = 0; xx < 4; ++xx) {
        const float* vx = V + (size_t)(x0 + xx) * NN + I0 + i0;
        float4 va = *reinterpret_cast<const float4*>(vx);       // v[i0..i0+3]
        float4 vb = *reinterpret_cast<const float4*>(vx + 4);   // v[i0+4..i0+7]
        const float vv[8] = {va.x, va.y, va.z, va.w, vb.x, vb.y, vb.z, vb.w};
        float sq = 0.0f, sc = 0.0f, sr = 0.0f;
        #pragma unroll
        for (int p = 0; p < 4; ++p) {
            float clo, chi;
            unpack2(acc[p][xx], clo, chi);
            sq += vv[2 * p] * clo + vv[2 * p + 1] * chi;
            sc += clo + chi;
            sr += vv[2 * p] * rlo[p] + vv[2 * p + 1] * rhi[p];
        }
        e[xx] = 2.0f * sq - sc - sr + s0;
    }

    #pragma unroll
    for (int off = 4; off >= 1; off >>= 1)
        #pragma unroll
        for (int xx = 0; xx < 4; ++xx)
            e[xx] += __shfl_xor_sync(0xffffffffu, e[xx], off, 8);

    if (ig == 0) {
        #pragma unroll
        for (int xx = 0; xx < 4; ++xx)
            atomicAdd(&out[x0 + xx], e[xx]);     // fire-and-forget -> REDG
    }
}

extern "C" void kernel_launch(void* const* d_in, const int* in_sizes, int n_in,
                              void* d_out, int out_size) {
    const float* V = (const float*)d_in[0];   // vector       [128,1024]
    const float* W = (const float*)d_in[1];   // interactions [1024,1024]
    if (n_in >= 2 && in_sizes[0] > in_sizes[1]) {
        V = (const float*)d_in[1];
        W = (const float*)d_in[0];
    }
    float* out = (float*)d_out;

    cudaMemsetAsync(out, 0, (size_t)out_size * sizeof(float));
    const int nblocks = (NT * (NT + 1) / 2) * 2;   // 136 upper tiles x 2 halves = 272
    potts_kernel<<<nblocks, 256>>>(V, W, out);
}